// round 16
// baseline (speedup 1.0000x reference)
#include <cuda_runtime.h>
#include <cuda.h>
#include <cuda_fp16.h>
#include <cstdint>
#include <cmath>

// Problem dims
#define DIM   4096
#define NTOK  8192
#define KCHUNK 64
#define KITERS (DIM / KCHUNK)   // 64
#define STAGES 3

#define W_BLOCKS 4096                          // 64x64 weight tiles
#define X_ITERS  4                             // grid-stride depth (MLP per thread)
#define X_BLOCKS ((NTOK * DIM / 4) / 256 / X_ITERS)   // 8192
#define FUSED_BLOCKS (W_BLOCKS + X_BLOCKS)

// ---------------- scratch ----------------
__device__ __half g_X[(size_t)NTOK * DIM];   // x in fp16, [tok][k] K-major
__device__ __half g_B[(size_t)DIM * DIM];    // w^T in fp16, [out][k] K-major
__device__ int    g_sum;                     // zero-init; self-resets each run
__device__ int    g_sumsq;                   // zero-init; self-resets each run
__device__ float  g_alpha;
__device__ unsigned g_blocks_done;           // zero-init; self-resets each run

// ---------------- PTX helpers (non-arch-specific) ----------------
__device__ __forceinline__ uint32_t smem_u32(const void* p) {
    uint32_t a;
    asm("{ .reg .u64 t; cvta.to.shared.u64 t, %1; cvt.u32.u64 %0, t; }" : "=r"(a) : "l"(p));
    return a;
}

#define MBARRIER_INIT(addr, count) \
    asm volatile("mbarrier.init.shared.b64 [%0], %1;" :: "r"((uint32_t)(addr)), "r"((uint32_t)(count)) : "memory")
#define MBARRIER_EXPECT_TX(addr, bytes) \
    asm volatile("mbarrier.arrive.expect_tx.shared.b64 _, [%0], %1;" :: "r"((uint32_t)(addr)), "r"((uint32_t)(bytes)) : "memory")

#define MBARRIER_WAIT_PARITY(mbar_smem_addr, phase_parity) do { \
    uint32_t _mbar = (uint32_t)(mbar_smem_addr); \
    uint32_t _parity = (uint32_t)(phase_parity); \
    uint32_t _done; \
    asm volatile( \
        "{\n\t.reg .pred p;\n\t" \
        "mbarrier.try_wait.parity.acquire.cta.shared::cta.b64 p, [%1], %2;\n\t" \
        "selp.b32 %0, 1, 0, p;\n\t}" \
        : "=r"(_done) : "r"(_mbar), "r"(_parity) : "memory"); \
    if (!_done) { \
        asm volatile( \
            "{\n\t.reg .pred P1;\n\t" \
            "WAIT_LOOP_%=:\n\t" \
            "mbarrier.try_wait.parity.acquire.cta.shared::cta.b64 P1, [%0], %1, 0x989680;\n\t" \
            "@P1 bra.uni WAIT_DONE_%=;\n\t" \
            "bra.uni WAIT_LOOP_%=;\n\t" \
            "WAIT_DONE_%=:\n\t}" \
            :: "r"(_mbar), "r"(_parity) : "memory"); \
    } \
} while (0)

#define TMA_LOAD_2D(smem_addr, map_ptr, cx, cy, mbar) \
    asm volatile( \
        "cp.async.bulk.tensor.2d.shared::cta.global.tile.mbarrier::complete_tx::bytes " \
        "[%0], [%1, {%2, %3}], [%4];" \
        :: "r"((uint32_t)(smem_addr)), "l"(map_ptr), "r"((int32_t)(cx)), "r"((int32_t)(cy)), \
           "r"((uint32_t)(mbar)) : "memory")

__device__ __forceinline__ void ldmatrix_x4(uint32_t r[4], uint32_t addr) {
    asm volatile("ldmatrix.sync.aligned.m8n8.x4.shared.b16 {%0,%1,%2,%3}, [%4];"
                 : "=r"(r[0]), "=r"(r[1]), "=r"(r[2]), "=r"(r[3]) : "r"(addr));
}

__device__ __forceinline__ void mma16816(float d[4], const uint32_t a[4],
                                         uint32_t b0, uint32_t b1) {
    asm volatile(
        "mma.sync.aligned.m16n8k16.row.col.f32.f16.f16.f32 "
        "{%0,%1,%2,%3}, {%4,%5,%6,%7}, {%8,%9}, {%0,%1,%2,%3};"
        : "+f"(d[0]), "+f"(d[1]), "+f"(d[2]), "+f"(d[3])
        : "r"(a[0]), "r"(a[1]), "r"(a[2]), "r"(a[3]), "r"(b0), "r"(b1));
}

// SW128 swizzle (matches CU_TENSOR_MAP_SWIZZLE_128B, tile base 1024-aligned)
__device__ __forceinline__ uint32_t swz(uint32_t o) { return o ^ ((o >> 3) & 0x70); }

// ---------------- kernel 1: FUSED quantize (W tiles + X stream MLP=4), fused alpha ----------------
__global__ void quant_fused_kernel(const float* __restrict__ mag, const float* __restrict__ sgn,
                                   const float* __restrict__ x) {
    __shared__ __align__(16) __half tile[64][68];
    const int t = threadIdx.x;

    if (blockIdx.x >= W_BLOCKS) {
        // ---- X path: fp32 -> fp16, grid-stride, 4 independent float4 loads (MLP=4) ----
        const size_t stride = (size_t)X_BLOCKS * 256 * 4;           // elements
        size_t i = ((size_t)(blockIdx.x - W_BLOCKS) * 256 + t) * 4;
        float4 v0 = *reinterpret_cast<const float4*>(x + i);
        float4 v1 = *reinterpret_cast<const float4*>(x + i + stride);
        float4 v2 = *reinterpret_cast<const float4*>(x + i + 2 * stride);
        float4 v3 = *reinterpret_cast<const float4*>(x + i + 3 * stride);
        *reinterpret_cast<__half2*>(&g_X[i])                  = __floats2half2_rn(v0.x, v0.y);
        *reinterpret_cast<__half2*>(&g_X[i + 2])              = __floats2half2_rn(v0.z, v0.w);
        *reinterpret_cast<__half2*>(&g_X[i + stride])         = __floats2half2_rn(v1.x, v1.y);
        *reinterpret_cast<__half2*>(&g_X[i + stride + 2])     = __floats2half2_rn(v1.z, v1.w);
        *reinterpret_cast<__half2*>(&g_X[i + 2 * stride])     = __floats2half2_rn(v2.x, v2.y);
        *reinterpret_cast<__half2*>(&g_X[i + 2 * stride + 2]) = __floats2half2_rn(v2.z, v2.w);
        *reinterpret_cast<__half2*>(&g_X[i + 3 * stride])     = __floats2half2_rn(v3.x, v3.y);
        *reinterpret_cast<__half2*>(&g_X[i + 3 * stride + 2]) = __floats2half2_rn(v3.z, v3.w);
        return;
    }

    // ---- W path: quantize + transpose + exact integer moments ----
    const int to = (blockIdx.x & 63) * 64;   // out dim tile
    const int ti = (blockIdx.x >> 6) * 64;   // in dim tile
    const int c4 = (t & 15) * 4;
    const int r0 = t >> 4;                   // 0..15
    const size_t plane = (size_t)DIM * DIM;

    int sum = 0, sq = 0;
#pragma unroll
    for (int p = 0; p < 4; ++p) {
        const int r = r0 + p * 16;
        const size_t idx = (size_t)(ti + r) * DIM + (to + c4);
        const float4 m0 = *reinterpret_cast<const float4*>(mag + idx);
        const float4 m1 = *reinterpret_cast<const float4*>(mag + idx + plane);
        const float4 m2 = *reinterpret_cast<const float4*>(mag + idx + 2 * plane);
        const float4 sg = *reinterpret_cast<const float4*>(sgn + idx);
        const float a0[4] = {m0.x, m0.y, m0.z, m0.w};
        const float a1[4] = {m1.x, m1.y, m1.z, m1.w};
        const float a2[4] = {m2.x, m2.y, m2.z, m2.w};
        const float as[4] = {sg.x, sg.y, sg.z, sg.w};
        float vf[4];
#pragma unroll
        for (int j = 0; j < 4; ++j) {
            int m = (a0[j] >= 0.f) * 4 + (a1[j] >= 0.f) * 2 + (a2[j] >= 0.f);
            int s = (as[j] >= 0.f) ? 1 : -1;
            int v = s * m;
            sum += v;
            sq += m * m;
            vf[j] = (float)v * 0.125f;       // exact in fp16
        }
        __half2 h01 = __floats2half2_rn(vf[0], vf[1]);
        __half2 h23 = __floats2half2_rn(vf[2], vf[3]);
        *reinterpret_cast<__half2*>(&tile[r][c4])     = h01;
        *reinterpret_cast<__half2*>(&tile[r][c4 + 2]) = h23;
    }
    __syncthreads();

    {
        const int col = t & 63;
        const int o0  = t >> 6;
#pragma unroll 4
        for (int p = 0; p < 16; ++p) {
            int o = o0 + p * 4;
            g_B[(size_t)(to + o) * DIM + (ti + col)] = tile[col][o];
        }
    }

    sum = __reduce_add_sync(0xFFFFFFFFu, sum);
    sq  = __reduce_add_sync(0xFFFFFFFFu, sq);
    if ((t & 31) == 0) {
        atomicAdd(&g_sum, sum);
        atomicAdd(&g_sumsq, sq);
    }

    // fused alpha: last W block computes it, then self-resets accumulators
    __syncthreads();
    if (t == 0) {
        __threadfence();
        unsigned old = atomicAdd(&g_blocks_done, 1u);
        if (old == W_BLOCKS - 1) {
            double N = (double)DIM * (double)DIM;
            double mean = (double)g_sum / N;
            double e2 = (double)g_sumsq / N;
            double var = e2 - mean * mean;            // var of v (w = v/8)
            double stdw = sqrt(var) * 0.125;
            double desired = sqrt(2.0 / (double)DIM);
            g_alpha = (float)(desired / (stdw + 1e-12));
            g_sum = 0;                                 // self-reset: no memsets needed
            g_sumsq = 0;
            g_blocks_done = 0;
            __threadfence();
        }
    }
}

// ---------------- kernel 2: mma.sync GEMM — FROZEN (measured best; 643 us, tensor 70.4%) ----------------
#define SM_A_OFF 1024
#define SM_B_OFF (1024 + STAGES * 16384)
#define SMEM_BYTES (SM_B_OFF + STAGES * 16384)   // 99328

__global__ void __launch_bounds__(256, 2)
gemm_kernel(const __grid_constant__ CUtensorMap tmA,
            const __grid_constant__ CUtensorMap tmB,
            float* __restrict__ out) {
    extern __shared__ char smem[];
    const uint32_t sb = smem_u32(smem);
    const uint32_t FULL = sb;           // 3 x 8B
    const int tid  = threadIdx.x;
    const int lane = tid & 31;
    const int wid  = tid >> 5;
    const int wm   = wid & 1;           // 0..1 -> 64-row slab
    const int wn   = wid >> 1;          // 0..3 -> 32-col slab

    const int m_base = blockIdx.y * 128;
    const int n_base = blockIdx.x * 128;

    if (tid == 0) {
#pragma unroll
        for (int s = 0; s < STAGES; ++s) MBARRIER_INIT(FULL + 8 * s, 1);
    }
    __syncthreads();

    if (tid == 0) {
#pragma unroll
        for (int s = 0; s < STAGES; ++s) {
            MBARRIER_EXPECT_TX(FULL + 8 * s, 32768);
            TMA_LOAD_2D(sb + SM_A_OFF + s * 16384, &tmA, s * KCHUNK, m_base, FULL + 8 * s);
            TMA_LOAD_2D(sb + SM_B_OFF + s * 16384, &tmB, s * KCHUNK, n_base, FULL + 8 * s);
        }
    }

    float acc[4][4][4];
#pragma unroll
    for (int i = 0; i < 4; ++i)
#pragma unroll
        for (int j = 0; j < 4; ++j)
#pragma unroll
            for (int e = 0; e < 4; ++e) acc[i][j][e] = 0.f;

    const uint32_t lrow = (uint32_t)(lane & 15);
    const uint32_t lkhi = (uint32_t)((lane >> 4) << 4);   // 0 or 16 bytes
    const uint32_t wrot = (uint32_t)(wid & 3) * 32;       // warp-staggered kk start

    for (int k = 0; k < KITERS; k += 2) {
#pragma unroll
        for (int half = 0; half < 2; ++half) {
            const int ch = k + half;                 // chunk index
            const int s  = ch % STAGES;
            MBARRIER_WAIT_PARITY(FULL + 8 * s, (ch / STAGES) & 1);

            const uint32_t sA = sb + SM_A_OFF + s * 16384;
            const uint32_t sB = sb + SM_B_OFF + s * 16384;

#pragma unroll
            for (int kk = 0; kk < 4; ++kk) {
                const uint32_t kb = (((uint32_t)kk * 32 + wrot) & 96) + lkhi;
                uint32_t ra[4][4];
#pragma unroll
                for (int mt = 0; mt < 4; ++mt)
                    ldmatrix_x4(ra[mt], sA + swz((wm * 64 + mt * 16 + lrow) * 128 + kb));
                uint32_t rb[2][4];
#pragma unroll
                for (int bt = 0; bt < 2; ++bt)
                    ldmatrix_x4(rb[bt], sB + swz((wn * 32 + bt * 16 + lrow) * 128 + kb));
#pragma unroll
                for (int mt = 0; mt < 4; ++mt)
#pragma unroll
                    for (int nt = 0; nt < 4; ++nt) {
                        const int j = nt >> 1, h = nt & 1;
                        mma16816(acc[mt][nt], ra[mt], rb[j][h], rb[j][h + 2]);
                    }
            }
        }
        __syncthreads();   // chunks k and k+1 fully consumed by all warps

        if (tid == 0) {
#pragma unroll
            for (int half = 0; half < 2; ++half) {
                const int kn = k + 3 + half;
                if (kn < KITERS) {
                    const int sn = kn % STAGES;      // just-freed stage
                    MBARRIER_EXPECT_TX(FULL + 8 * sn, 32768);
                    TMA_LOAD_2D(sb + SM_A_OFF + sn * 16384, &tmA, kn * KCHUNK, m_base, FULL + 8 * sn);
                    TMA_LOAD_2D(sb + SM_B_OFF + sn * 16384, &tmB, kn * KCHUNK, n_base, FULL + 8 * sn);
                }
            }
        }
    }

    // epilogue: scale by alpha, write f32
    const float alpha = g_alpha;
    const int r = lane >> 2, c = (lane & 3) * 2;
    const int m0 = m_base + wm * 64;
    const int n0 = n_base + wn * 32;
#pragma unroll
    for (int mt = 0; mt < 4; ++mt)
#pragma unroll
        for (int nt = 0; nt < 4; ++nt) {
            float2 v0 = make_float2(acc[mt][nt][0] * alpha, acc[mt][nt][1] * alpha);
            float2 v1 = make_float2(acc[mt][nt][2] * alpha, acc[mt][nt][3] * alpha);
            size_t row0 = (size_t)(m0 + mt * 16 + r) * DIM + (n0 + nt * 8 + c);
            *reinterpret_cast<float2*>(out + row0)            = v0;
            *reinterpret_cast<float2*>(out + row0 + 8 * DIM)  = v1;
        }
}

// ---------------- host: driver entry point via runtime (no -lcuda) ----------------
typedef CUresult (*PFN_encodeTiled)(
    CUtensorMap*, CUtensorMapDataType, cuuint32_t, void*,
    const cuuint64_t*, const cuuint64_t*, const cuuint32_t*, const cuuint32_t*,
    CUtensorMapInterleave, CUtensorMapSwizzle, CUtensorMapL2promotion,
    CUtensorMapFloatOOBfill);

static PFN_encodeTiled get_encode_fn() {
    static PFN_encodeTiled fn = nullptr;
    if (!fn) {
        void* p = nullptr;
#if CUDART_VERSION >= 12050
        cudaDriverEntryPointQueryResult st;
        cudaGetDriverEntryPointByVersion("cuTensorMapEncodeTiled", &p, 12000,
                                         cudaEnableDefault, &st);
        if (!p) cudaGetDriverEntryPoint("cuTensorMapEncodeTiled", &p,
                                        cudaEnableDefault, &st);
#else
        cudaDriverEntryPointQueryResult st;
        cudaGetDriverEntryPoint("cuTensorMapEncodeTiled", &p, cudaEnableDefault, &st);
#endif
        fn = (PFN_encodeTiled)p;
    }
    return fn;
}

// ---------------- launch ----------------
extern "C" void kernel_launch(void* const* d_in, const int* in_sizes, int n_in,
                              void* d_out, int out_size) {
    const float* x = nullptr;
    const float* mag = nullptr;
    const float* sgn = nullptr;
    for (int i = 0; i < n_in; ++i) {
        if (in_sizes[i] == NTOK * DIM)            x   = (const float*)d_in[i];
        else if (in_sizes[i] == 3 * DIM * DIM)    mag = (const float*)d_in[i];
        else if (in_sizes[i] == DIM * DIM)        sgn = (const float*)d_in[i];
    }
    float* out = (float*)d_out;

    void *pX, *pB;
    cudaGetSymbolAddress(&pX, g_X);
    cudaGetSymbolAddress(&pB, g_B);

    quant_fused_kernel<<<FUSED_BLOCKS, 256>>>(mag, sgn, x);

    PFN_encodeTiled encode = get_encode_fn();

    CUtensorMap tmA{}, tmB{};
    {
        cuuint64_t dimsA[2] = {DIM, NTOK};
        cuuint64_t strA[1]  = {DIM * sizeof(__half)};
        cuuint32_t boxA[2]  = {KCHUNK, 128};   // 64 fp16 = 128B inner = SW128 atom
        cuuint32_t es[2]    = {1, 1};
        encode(&tmA, CU_TENSOR_MAP_DATA_TYPE_FLOAT16, 2, pX,
               dimsA, strA, boxA, es,
               CU_TENSOR_MAP_INTERLEAVE_NONE, CU_TENSOR_MAP_SWIZZLE_128B,
               CU_TENSOR_MAP_L2_PROMOTION_L2_128B,
               CU_TENSOR_MAP_FLOAT_OOB_FILL_NONE);
        cuuint64_t dimsB[2] = {DIM, DIM};
        cuuint64_t strB[1]  = {DIM * sizeof(__half)};
        cuuint32_t boxB[2]  = {KCHUNK, 128};
        encode(&tmB, CU_TENSOR_MAP_DATA_TYPE_FLOAT16, 2, pB,
               dimsB, strB, boxB, es,
               CU_TENSOR_MAP_INTERLEAVE_NONE, CU_TENSOR_MAP_SWIZZLE_128B,
               CU_TENSOR_MAP_L2_PROMOTION_L2_128B,
               CU_TENSOR_MAP_FLOAT_OOB_FILL_NONE);
    }

    cudaFuncSetAttribute(gemm_kernel, cudaFuncAttributeMaxDynamicSharedMemorySize, SMEM_BYTES);
    gemm_kernel<<<dim3(DIM / 128, NTOK / 128), 256, SMEM_BYTES>>>(tmA, tmB, out);
}

// round 17
// speedup vs baseline: 1.0023x; 1.0023x over previous
#include <cuda_runtime.h>
#include <cuda.h>
#include <cuda_fp16.h>
#include <cstdint>
#include <cmath>

// Problem dims
#define DIM   4096
#define NTOK  8192
#define KCHUNK 64
#define KITERS (DIM / KCHUNK)   // 64
#define STAGES 3

#define W_BLOCKS 4096                          // 64x64 weight tiles
#define X_ITERS  4                             // grid-stride depth (MLP per thread)
#define X_BLOCKS ((NTOK * DIM / 4) / 256 / X_ITERS)   // 8192
#define FUSED_BLOCKS (W_BLOCKS + X_BLOCKS)

// ---------------- scratch ----------------
__device__ __half g_X[(size_t)NTOK * DIM];   // x in fp16, [tok][k] K-major
__device__ __half g_B[(size_t)DIM * DIM];    // w^T in fp16, [out][k] K-major
__device__ int    g_sum;                     // zero-init; self-resets each run
__device__ int    g_sumsq;                   // zero-init; self-resets each run
__device__ float  g_alpha;
__device__ unsigned g_blocks_done;           // zero-init; self-resets each run

// ---------------- PTX helpers (non-arch-specific) ----------------
__device__ __forceinline__ uint32_t smem_u32(const void* p) {
    uint32_t a;
    asm("{ .reg .u64 t; cvta.to.shared.u64 t, %1; cvt.u32.u64 %0, t; }" : "=r"(a) : "l"(p));
    return a;
}

#define MBARRIER_INIT(addr, count) \
    asm volatile("mbarrier.init.shared.b64 [%0], %1;" :: "r"((uint32_t)(addr)), "r"((uint32_t)(count)) : "memory")
#define MBARRIER_EXPECT_TX(addr, bytes) \
    asm volatile("mbarrier.arrive.expect_tx.shared.b64 _, [%0], %1;" :: "r"((uint32_t)(addr)), "r"((uint32_t)(bytes)) : "memory")

#define MBARRIER_WAIT_PARITY(mbar_smem_addr, phase_parity) do { \
    uint32_t _mbar = (uint32_t)(mbar_smem_addr); \
    uint32_t _parity = (uint32_t)(phase_parity); \
    uint32_t _done; \
    asm volatile( \
        "{\n\t.reg .pred p;\n\t" \
        "mbarrier.try_wait.parity.acquire.cta.shared::cta.b64 p, [%1], %2;\n\t" \
        "selp.b32 %0, 1, 0, p;\n\t}" \
        : "=r"(_done) : "r"(_mbar), "r"(_parity) : "memory"); \
    if (!_done) { \
        asm volatile( \
            "{\n\t.reg .pred P1;\n\t" \
            "WAIT_LOOP_%=:\n\t" \
            "mbarrier.try_wait.parity.acquire.cta.shared::cta.b64 P1, [%0], %1, 0x989680;\n\t" \
            "@P1 bra.uni WAIT_DONE_%=;\n\t" \
            "bra.uni WAIT_LOOP_%=;\n\t" \
            "WAIT_DONE_%=:\n\t}" \
            :: "r"(_mbar), "r"(_parity) : "memory"); \
    } \
} while (0)

#define TMA_LOAD_2D(smem_addr, map_ptr, cx, cy, mbar) \
    asm volatile( \
        "cp.async.bulk.tensor.2d.shared::cta.global.tile.mbarrier::complete_tx::bytes " \
        "[%0], [%1, {%2, %3}], [%4];" \
        :: "r"((uint32_t)(smem_addr)), "l"(map_ptr), "r"((int32_t)(cx)), "r"((int32_t)(cy)), \
           "r"((uint32_t)(mbar)) : "memory")

__device__ __forceinline__ void ldmatrix_x4(uint32_t r[4], uint32_t addr) {
    asm volatile("ldmatrix.sync.aligned.m8n8.x4.shared.b16 {%0,%1,%2,%3}, [%4];"
                 : "=r"(r[0]), "=r"(r[1]), "=r"(r[2]), "=r"(r[3]) : "r"(addr));
}

__device__ __forceinline__ void mma16816(float d[4], const uint32_t a[4],
                                         uint32_t b0, uint32_t b1) {
    asm volatile(
        "mma.sync.aligned.m16n8k16.row.col.f32.f16.f16.f32 "
        "{%0,%1,%2,%3}, {%4,%5,%6,%7}, {%8,%9}, {%0,%1,%2,%3};"
        : "+f"(d[0]), "+f"(d[1]), "+f"(d[2]), "+f"(d[3])
        : "r"(a[0]), "r"(a[1]), "r"(a[2]), "r"(a[3]), "r"(b0), "r"(b1));
}

// SW128 swizzle (matches CU_TENSOR_MAP_SWIZZLE_128B, tile base 1024-aligned)
__device__ __forceinline__ uint32_t swz(uint32_t o) { return o ^ ((o >> 3) & 0x70); }

// ---------------- kernel 1: FUSED quantize (W tiles + X stream MLP=4), fused alpha ----------------
__global__ void quant_fused_kernel(const float* __restrict__ mag, const float* __restrict__ sgn,
                                   const float* __restrict__ x) {
    __shared__ __align__(16) __half tile[64][68];
    const int t = threadIdx.x;

    if (blockIdx.x >= W_BLOCKS) {
        // ---- X path: fp32 -> fp16, grid-stride, 4 independent float4 loads (MLP=4) ----
        const size_t stride = (size_t)X_BLOCKS * 256 * 4;           // elements
        size_t i = ((size_t)(blockIdx.x - W_BLOCKS) * 256 + t) * 4;
        float4 v0 = *reinterpret_cast<const float4*>(x + i);
        float4 v1 = *reinterpret_cast<const float4*>(x + i + stride);
        float4 v2 = *reinterpret_cast<const float4*>(x + i + 2 * stride);
        float4 v3 = *reinterpret_cast<const float4*>(x + i + 3 * stride);
        *reinterpret_cast<__half2*>(&g_X[i])                  = __floats2half2_rn(v0.x, v0.y);
        *reinterpret_cast<__half2*>(&g_X[i + 2])              = __floats2half2_rn(v0.z, v0.w);
        *reinterpret_cast<__half2*>(&g_X[i + stride])         = __floats2half2_rn(v1.x, v1.y);
        *reinterpret_cast<__half2*>(&g_X[i + stride + 2])     = __floats2half2_rn(v1.z, v1.w);
        *reinterpret_cast<__half2*>(&g_X[i + 2 * stride])     = __floats2half2_rn(v2.x, v2.y);
        *reinterpret_cast<__half2*>(&g_X[i + 2 * stride + 2]) = __floats2half2_rn(v2.z, v2.w);
        *reinterpret_cast<__half2*>(&g_X[i + 3 * stride])     = __floats2half2_rn(v3.x, v3.y);
        *reinterpret_cast<__half2*>(&g_X[i + 3 * stride + 2]) = __floats2half2_rn(v3.z, v3.w);
        return;
    }

    // ---- W path: quantize + transpose + exact integer moments ----
    const int to = (blockIdx.x & 63) * 64;   // out dim tile
    const int ti = (blockIdx.x >> 6) * 64;   // in dim tile
    const int c4 = (t & 15) * 4;
    const int r0 = t >> 4;                   // 0..15
    const size_t plane = (size_t)DIM * DIM;

    int sum = 0, sq = 0;
#pragma unroll
    for (int p = 0; p < 4; ++p) {
        const int r = r0 + p * 16;
        const size_t idx = (size_t)(ti + r) * DIM + (to + c4);
        const float4 m0 = *reinterpret_cast<const float4*>(mag + idx);
        const float4 m1 = *reinterpret_cast<const float4*>(mag + idx + plane);
        const float4 m2 = *reinterpret_cast<const float4*>(mag + idx + 2 * plane);
        const float4 sg = *reinterpret_cast<const float4*>(sgn + idx);
        const float a0[4] = {m0.x, m0.y, m0.z, m0.w};
        const float a1[4] = {m1.x, m1.y, m1.z, m1.w};
        const float a2[4] = {m2.x, m2.y, m2.z, m2.w};
        const float as[4] = {sg.x, sg.y, sg.z, sg.w};
        float vf[4];
#pragma unroll
        for (int j = 0; j < 4; ++j) {
            int m = (a0[j] >= 0.f) * 4 + (a1[j] >= 0.f) * 2 + (a2[j] >= 0.f);
            int s = (as[j] >= 0.f) ? 1 : -1;
            int v = s * m;
            sum += v;
            sq += m * m;
            vf[j] = (float)v * 0.125f;       // exact in fp16
        }
        __half2 h01 = __floats2half2_rn(vf[0], vf[1]);
        __half2 h23 = __floats2half2_rn(vf[2], vf[3]);
        *reinterpret_cast<__half2*>(&tile[r][c4])     = h01;
        *reinterpret_cast<__half2*>(&tile[r][c4 + 2]) = h23;
    }
    __syncthreads();

    {
        const int col = t & 63;
        const int o0  = t >> 6;
#pragma unroll 4
        for (int p = 0; p < 16; ++p) {
            int o = o0 + p * 4;
            g_B[(size_t)(to + o) * DIM + (ti + col)] = tile[col][o];
        }
    }

    sum = __reduce_add_sync(0xFFFFFFFFu, sum);
    sq  = __reduce_add_sync(0xFFFFFFFFu, sq);
    if ((t & 31) == 0) {
        atomicAdd(&g_sum, sum);
        atomicAdd(&g_sumsq, sq);
    }

    // fused alpha: last W block computes it, then self-resets accumulators
    __syncthreads();
    if (t == 0) {
        __threadfence();
        unsigned old = atomicAdd(&g_blocks_done, 1u);
        if (old == W_BLOCKS - 1) {
            double N = (double)DIM * (double)DIM;
            double mean = (double)g_sum / N;
            double e2 = (double)g_sumsq / N;
            double var = e2 - mean * mean;            // var of v (w = v/8)
            double stdw = sqrt(var) * 0.125;
            double desired = sqrt(2.0 / (double)DIM);
            g_alpha = (float)(desired / (stdw + 1e-12));
            g_sum = 0;                                 // self-reset: no memsets needed
            g_sumsq = 0;
            g_blocks_done = 0;
            __threadfence();
        }
    }
}

// ---------------- kernel 2: mma.sync GEMM — FROZEN (measured best; 643 us, tensor 70.4%) ----------------
#define SM_A_OFF 1024
#define SM_B_OFF (1024 + STAGES * 16384)
#define SMEM_BYTES (SM_B_OFF + STAGES * 16384)   // 99328

__global__ void __launch_bounds__(256, 2)
gemm_kernel(const __grid_constant__ CUtensorMap tmA,
            const __grid_constant__ CUtensorMap tmB,
            float* __restrict__ out) {
    extern __shared__ char smem[];
    const uint32_t sb = smem_u32(smem);
    const uint32_t FULL = sb;           // 3 x 8B
    const int tid  = threadIdx.x;
    const int lane = tid & 31;
    const int wid  = tid >> 5;
    const int wm   = wid & 1;           // 0..1 -> 64-row slab
    const int wn   = wid >> 1;          // 0..3 -> 32-col slab

    const int m_base = blockIdx.y * 128;
    const int n_base = blockIdx.x * 128;

    if (tid == 0) {
#pragma unroll
        for (int s = 0; s < STAGES; ++s) MBARRIER_INIT(FULL + 8 * s, 1);
    }
    __syncthreads();

    if (tid == 0) {
#pragma unroll
        for (int s = 0; s < STAGES; ++s) {
            MBARRIER_EXPECT_TX(FULL + 8 * s, 32768);
            TMA_LOAD_2D(sb + SM_A_OFF + s * 16384, &tmA, s * KCHUNK, m_base, FULL + 8 * s);
            TMA_LOAD_2D(sb + SM_B_OFF + s * 16384, &tmB, s * KCHUNK, n_base, FULL + 8 * s);
        }
    }

    float acc[4][4][4];
#pragma unroll
    for (int i = 0; i < 4; ++i)
#pragma unroll
        for (int j = 0; j < 4; ++j)
#pragma unroll
            for (int e = 0; e < 4; ++e) acc[i][j][e] = 0.f;

    const uint32_t lrow = (uint32_t)(lane & 15);
    const uint32_t lkhi = (uint32_t)((lane >> 4) << 4);   // 0 or 16 bytes
    const uint32_t wrot = (uint32_t)(wid & 3) * 32;       // warp-staggered kk start

    for (int k = 0; k < KITERS; k += 2) {
#pragma unroll
        for (int half = 0; half < 2; ++half) {
            const int ch = k + half;                 // chunk index
            const int s  = ch % STAGES;
            MBARRIER_WAIT_PARITY(FULL + 8 * s, (ch / STAGES) & 1);

            const uint32_t sA = sb + SM_A_OFF + s * 16384;
            const uint32_t sB = sb + SM_B_OFF + s * 16384;

#pragma unroll
            for (int kk = 0; kk < 4; ++kk) {
                const uint32_t kb = (((uint32_t)kk * 32 + wrot) & 96) + lkhi;
                uint32_t ra[4][4];
#pragma unroll
                for (int mt = 0; mt < 4; ++mt)
                    ldmatrix_x4(ra[mt], sA + swz((wm * 64 + mt * 16 + lrow) * 128 + kb));
                uint32_t rb[2][4];
#pragma unroll
                for (int bt = 0; bt < 2; ++bt)
                    ldmatrix_x4(rb[bt], sB + swz((wn * 32 + bt * 16 + lrow) * 128 + kb));
#pragma unroll
                for (int mt = 0; mt < 4; ++mt)
#pragma unroll
                    for (int nt = 0; nt < 4; ++nt) {
                        const int j = nt >> 1, h = nt & 1;
                        mma16816(acc[mt][nt], ra[mt], rb[j][h], rb[j][h + 2]);
                    }
            }
        }
        __syncthreads();   // chunks k and k+1 fully consumed by all warps

        if (tid == 0) {
#pragma unroll
            for (int half = 0; half < 2; ++half) {
                const int kn = k + 3 + half;
                if (kn < KITERS) {
                    const int sn = kn % STAGES;      // just-freed stage
                    MBARRIER_EXPECT_TX(FULL + 8 * sn, 32768);
                    TMA_LOAD_2D(sb + SM_A_OFF + sn * 16384, &tmA, kn * KCHUNK, m_base, FULL + 8 * sn);
                    TMA_LOAD_2D(sb + SM_B_OFF + sn * 16384, &tmB, kn * KCHUNK, n_base, FULL + 8 * sn);
                }
            }
        }
    }

    // epilogue: scale by alpha, write f32
    const float alpha = g_alpha;
    const int r = lane >> 2, c = (lane & 3) * 2;
    const int m0 = m_base + wm * 64;
    const int n0 = n_base + wn * 32;
#pragma unroll
    for (int mt = 0; mt < 4; ++mt)
#pragma unroll
        for (int nt = 0; nt < 4; ++nt) {
            float2 v0 = make_float2(acc[mt][nt][0] * alpha, acc[mt][nt][1] * alpha);
            float2 v1 = make_float2(acc[mt][nt][2] * alpha, acc[mt][nt][3] * alpha);
            size_t row0 = (size_t)(m0 + mt * 16 + r) * DIM + (n0 + nt * 8 + c);
            *reinterpret_cast<float2*>(out + row0)            = v0;
            *reinterpret_cast<float2*>(out + row0 + 8 * DIM)  = v1;
        }
}

// ---------------- host: driver entry point via runtime (no -lcuda) ----------------
typedef CUresult (*PFN_encodeTiled)(
    CUtensorMap*, CUtensorMapDataType, cuuint32_t, void*,
    const cuuint64_t*, const cuuint64_t*, const cuuint32_t*, const cuuint32_t*,
    CUtensorMapInterleave, CUtensorMapSwizzle, CUtensorMapL2promotion,
    CUtensorMapFloatOOBfill);

static PFN_encodeTiled get_encode_fn() {
    static PFN_encodeTiled fn = nullptr;
    if (!fn) {
        void* p = nullptr;
#if CUDART_VERSION >= 12050
        cudaDriverEntryPointQueryResult st;
        cudaGetDriverEntryPointByVersion("cuTensorMapEncodeTiled", &p, 12000,
                                         cudaEnableDefault, &st);
        if (!p) cudaGetDriverEntryPoint("cuTensorMapEncodeTiled", &p,
                                        cudaEnableDefault, &st);
#else
        cudaDriverEntryPointQueryResult st;
        cudaGetDriverEntryPoint("cuTensorMapEncodeTiled", &p, cudaEnableDefault, &st);
#endif
        fn = (PFN_encodeTiled)p;
    }
    return fn;
}

// ---------------- launch ----------------
extern "C" void kernel_launch(void* const* d_in, const int* in_sizes, int n_in,
                              void* d_out, int out_size) {
    const float* x = nullptr;
    const float* mag = nullptr;
    const float* sgn = nullptr;
    for (int i = 0; i < n_in; ++i) {
        if (in_sizes[i] == NTOK * DIM)            x   = (const float*)d_in[i];
        else if (in_sizes[i] == 3 * DIM * DIM)    mag = (const float*)d_in[i];
        else if (in_sizes[i] == DIM * DIM)        sgn = (const float*)d_in[i];
    }
    float* out = (float*)d_out;

    void *pX, *pB;
    cudaGetSymbolAddress(&pX, g_X);
    cudaGetSymbolAddress(&pB, g_B);

    quant_fused_kernel<<<FUSED_BLOCKS, 256>>>(mag, sgn, x);

    PFN_encodeTiled encode = get_encode_fn();

    CUtensorMap tmA{}, tmB{};
    {
        cuuint64_t dimsA[2] = {DIM, NTOK};
        cuuint64_t strA[1]  = {DIM * sizeof(__half)};
        cuuint32_t boxA[2]  = {KCHUNK, 128};   // 64 fp16 = 128B inner = SW128 atom
        cuuint32_t es[2]    = {1, 1};
        encode(&tmA, CU_TENSOR_MAP_DATA_TYPE_FLOAT16, 2, pX,
               dimsA, strA, boxA, es,
               CU_TENSOR_MAP_INTERLEAVE_NONE, CU_TENSOR_MAP_SWIZZLE_128B,
               CU_TENSOR_MAP_L2_PROMOTION_L2_128B,
               CU_TENSOR_MAP_FLOAT_OOB_FILL_NONE);
        cuuint64_t dimsB[2] = {DIM, DIM};
        cuuint64_t strB[1]  = {DIM * sizeof(__half)};
        cuuint32_t boxB[2]  = {KCHUNK, 128};
        encode(&tmB, CU_TENSOR_MAP_DATA_TYPE_FLOAT16, 2, pB,
               dimsB, strB, boxB, es,
               CU_TENSOR_MAP_INTERLEAVE_NONE, CU_TENSOR_MAP_SWIZZLE_128B,
               CU_TENSOR_MAP_L2_PROMOTION_L2_128B,
               CU_TENSOR_MAP_FLOAT_OOB_FILL_NONE);
    }

    cudaFuncSetAttribute(gemm_kernel, cudaFuncAttributeMaxDynamicSharedMemorySize, SMEM_BYTES);
    gemm_kernel<<<dim3(DIM / 128, NTOK / 128), 256, SMEM_BYTES>>>(tmA, tmB, out);
}